// round 4
// baseline (speedup 1.0000x reference)
#include <cuda_runtime.h>

// LIF scan: x (N=32, T=16, C=128, H=32, W=32) f32 -> spikes same shape.
// v = v*0.5 + x_t; spike = (v >= 1); v -= spike.  v_init structurally zero.
//
// HBM-bound streaming kernel. Measured across R1-R3: plain (default .wb/.ca)
// loads+stores give the best DRAM efficiency (6.79 TB/s effective vs 6.70 with
// .cs hints). This version: plain accesses + v_init elision + 4-deep load
// batching (regs ~40, occ ~66%, MLP=4/thread).

#define N_BATCH 32
#define T_STEPS 16
#define S_ELEMS (128 * 32 * 32)      // 131072 elements per (n,t) plane
#define SV (S_ELEMS / 4)             // 32768 float4 per plane

__device__ __forceinline__ void lif_step(float& v, float xv, float& sp) {
    v = v * 0.5f + xv;
    sp = (v >= 1.0f) ? 1.0f : 0.0f;
    v -= sp;
}

__device__ __forceinline__ float4 lif_step4(float4& v, float4 xt) {
    float4 sp;
    lif_step(v.x, xt.x, sp.x);
    lif_step(v.y, xt.y, sp.y);
    lif_step(v.z, xt.z, sp.z);
    lif_step(v.w, xt.w, sp.w);
    return sp;
}

__global__ __launch_bounds__(256) void lif_kernel(
    const float4* __restrict__ x,
    float4* __restrict__ out)
{
    const int tid = blockIdx.x * blockDim.x + threadIdx.x;   // 0 .. N_BATCH*SV-1
    const int n  = tid >> 15;          // tid / SV
    const int sv = tid & (SV - 1);     // tid % SV

    float4 v = make_float4(0.0f, 0.0f, 0.0f, 0.0f);   // v_init == 0

    const float4* xp = x + (size_t)n * T_STEPS * SV + sv;
    float4*       op = out + (size_t)n * T_STEPS * SV + sv;

#pragma unroll
    for (int tb = 0; tb < T_STEPS; tb += 4) {
        // 4 back-to-back plain LDG.128 (MLP=4)
        float4 x0 = xp[(size_t)(tb + 0) * SV];
        float4 x1 = xp[(size_t)(tb + 1) * SV];
        float4 x2 = xp[(size_t)(tb + 2) * SV];
        float4 x3 = xp[(size_t)(tb + 3) * SV];

        float4 s0 = lif_step4(v, x0);
        float4 s1 = lif_step4(v, x1);
        float4 s2 = lif_step4(v, x2);
        float4 s3 = lif_step4(v, x3);

        op[(size_t)(tb + 0) * SV] = s0;
        op[(size_t)(tb + 1) * SV] = s1;
        op[(size_t)(tb + 2) * SV] = s2;
        op[(size_t)(tb + 3) * SV] = s3;
    }
}

extern "C" void kernel_launch(void* const* d_in, const int* in_sizes, int n_in,
                              void* d_out, int out_size)
{
    const float4* x   = (const float4*)d_in[0];
    float4*       out = (float4*)d_out;

    const int total_threads = N_BATCH * SV;          // 1,048,576
    const int block = 256;
    const int grid  = total_threads / block;         // 4096

    lif_kernel<<<grid, block>>>(x, out);
}

// round 7
// speedup vs baseline: 1.0058x; 1.0058x over previous
#include <cuda_runtime.h>
#include <cstdint>

// LIF scan: x (N=32, T=16, C=128, H=32, W=32) f32 -> spikes same shape.
// v = v*0.5 + x_t; spike = (v >= 1); v -= spike.  v_init structurally zero.
//
// At the LTS/DRAM ceiling (~6.7 TB/s measured across R1-R4). This round:
// 256-bit global accesses (sm_103a LDG.256/STG.256 via ld/st.global.v8.b32).
// Each thread owns 8 consecutive floats (32B, alignment guaranteed: all
// plane strides are multiples of 128B). Halves LDG/STG count and doubles
// per-instruction contiguous footprint (1024B/warp) for longer MC bursts.

#define N_BATCH 32
#define T_STEPS 16
#define S_ELEMS (128 * 32 * 32)      // 131072 elements per (n,t) plane
#define SV8 (S_ELEMS / 8)            // 16384 8-float groups per plane

struct f8 { float v[8]; };

__device__ __forceinline__ f8 ldg256(const float* p) {
    f8 r;
    asm volatile("ld.global.v8.b32 {%0,%1,%2,%3,%4,%5,%6,%7}, [%8];"
                 : "=f"(r.v[0]), "=f"(r.v[1]), "=f"(r.v[2]), "=f"(r.v[3]),
                   "=f"(r.v[4]), "=f"(r.v[5]), "=f"(r.v[6]), "=f"(r.v[7])
                 : "l"(p));
    return r;
}

__device__ __forceinline__ void stg256(float* p, const f8& r) {
    asm volatile("st.global.v8.b32 [%0], {%1,%2,%3,%4,%5,%6,%7,%8};"
                 :: "l"(p),
                    "f"(r.v[0]), "f"(r.v[1]), "f"(r.v[2]), "f"(r.v[3]),
                    "f"(r.v[4]), "f"(r.v[5]), "f"(r.v[6]), "f"(r.v[7])
                 : "memory");
}

__device__ __forceinline__ void lif_step8(float* __restrict__ v, f8& x) {
#pragma unroll
    for (int i = 0; i < 8; ++i) {
        float vi = v[i] * 0.5f + x.v[i];
        float sp = (vi >= 1.0f) ? 1.0f : 0.0f;
        v[i] = vi - sp;
        x.v[i] = sp;                 // spike overwrites the input slot
    }
}

__global__ __launch_bounds__(256) void lif_kernel(
    const float* __restrict__ x,
    float* __restrict__ out)
{
    const int tid = blockIdx.x * blockDim.x + threadIdx.x;  // 0 .. N_BATCH*SV8-1
    const int n  = tid >> 14;           // tid / SV8
    const int g  = tid & (SV8 - 1);     // tid % SV8

    const float* xp = x   + ((size_t)n * T_STEPS * SV8 + g) * 8;
    float*       op = out + ((size_t)n * T_STEPS * SV8 + g) * 8;
    const size_t stride = (size_t)SV8 * 8;   // one timestep plane, in floats

    float v[8];
#pragma unroll
    for (int i = 0; i < 8; ++i) v[i] = 0.0f;   // v_init == 0

#pragma unroll
    for (int tb = 0; tb < T_STEPS; tb += 4) {
        // 4 back-to-back LDG.256 (MLP=4, 128B/thread in flight)
        f8 x0 = ldg256(xp + (size_t)(tb + 0) * stride);
        f8 x1 = ldg256(xp + (size_t)(tb + 1) * stride);
        f8 x2 = ldg256(xp + (size_t)(tb + 2) * stride);
        f8 x3 = ldg256(xp + (size_t)(tb + 3) * stride);

        lif_step8(v, x0);
        lif_step8(v, x1);
        lif_step8(v, x2);
        lif_step8(v, x3);

        stg256(op + (size_t)(tb + 0) * stride, x0);
        stg256(op + (size_t)(tb + 1) * stride, x1);
        stg256(op + (size_t)(tb + 2) * stride, x2);
        stg256(op + (size_t)(tb + 3) * stride, x3);
    }
}

extern "C" void kernel_launch(void* const* d_in, const int* in_sizes, int n_in,
                              void* d_out, int out_size)
{
    const float* x   = (const float*)d_in[0];
    float*       out = (float*)d_out;

    const int total_threads = N_BATCH * SV8;   // 524,288
    const int block = 256;
    const int grid  = total_threads / block;   // 2048

    lif_kernel<<<grid, block>>>(x, out);
}